// round 11
// baseline (speedup 1.0000x reference)
#include <cuda_runtime.h>
#include <cuda_fp16.h>
#include <cstdint>

// ============================================================================
// QuantizedLinear, sm_103 base-PTX build (no tcgen05 in this toolchain).
// R3: classic fp16 HMMA native, 1437us (66.5%).  R4: 2 CTAs/SM -> 1269us.
// R5: decoupled mbarrier ring -> 1126us (86.1%). R6: hoisted wait -> 1117us (86.6%).
// R7: rotation (DVFS-noise).  R8: persistent 2-tile: regression, reverted.
// R9: early stage release + direct-STG epilogue -> 1112us BUT rel_err
//     2.09e-4 -> 6.19e-4: the post-LDS-issue release RACES with the producer
//     DMA (issue != SMEM read complete under deep L1tex queues).
// R10: consume-before-release. At kk=3: 9 MMAs that consume ALL fragment
//     registers (mt0 x nt0..7, then mt1 x nt0) -> scoreboard proves every
//     LDS completed -> arrive(empty) -> hoisted full-wait -> remaining 7 MMAs.
//     Keeps the early-release overlap, zero race window.
//   x -> fp16 (rel sigma ~1.7e-4), wq (0..126) -> fp16 exact,
//   y = (x_h @ w_h^T)*scale + bias, fp32 accum.
// ============================================================================

#define M_TOTAL 16384
#define N_TOTAL 4096
#define K_TOTAL 4096
#define NUM_KS  64            // K chunks of 64
#define NUM_MT  128           // M tiles of 128
#define NUM_NT  32            // N tiles of 128
#define STAGES  3

#define A_CHUNK_BYTES 16384   // 128m x 64k fp16, frag-ordered
#define B_CHUNK_BYTES 16384   // 128n x 64k fp16, frag-ordered (paired 16B slots)
#define STAGE_BYTES   (A_CHUNK_BYTES + B_CHUNK_BYTES)   // 32768

#define SMEM_BIAS   512
#define SMEM_STAGE0 1024
#define DYN_SMEM    (SMEM_STAGE0 + STAGES * STAGE_BYTES)  // 99328 -> 2 CTAs/SM

__device__ __align__(1024) unsigned char g_A[(size_t)NUM_MT * NUM_KS * A_CHUNK_BYTES]; // 128 MB
__device__ __align__(1024) unsigned char g_B[(size_t)NUM_NT * NUM_KS * B_CHUNK_BYTES]; //  32 MB

// ---------------------------------------------------------------------------
__device__ __forceinline__ uint32_t smem_u32(const void* p) {
    uint32_t a;
    asm("{ .reg .u64 t; cvta.to.shared.u64 t, %1; cvt.u32.u64 %0, t; }" : "=r"(a) : "l"(p));
    return a;
}

#define MBARRIER_INIT(addr, cnt) \
    asm volatile("mbarrier.init.shared.b64 [%0], %1;" :: "r"((uint32_t)(addr)), "r"((uint32_t)(cnt)) : "memory")
#define MBARRIER_EXPECT_TX(addr, bytes) \
    asm volatile("mbarrier.arrive.expect_tx.shared.b64 _, [%0], %1;" :: "r"((uint32_t)(addr)), "r"((uint32_t)(bytes)) : "memory")
#define MBARRIER_ARRIVE(addr) \
    asm volatile("mbarrier.arrive.shared.b64 _, [%0];" :: "r"((uint32_t)(addr)) : "memory")

#define MBARRIER_WAIT_PARITY(addr, parity) do {                                   \
    uint32_t _m = (uint32_t)(addr); uint32_t _p = (uint32_t)(parity); uint32_t _d;\
    asm volatile("{\n\t.reg .pred p;\n\t"                                         \
        "mbarrier.try_wait.parity.acquire.cta.shared::cta.b64 p, [%1], %2;\n\t"   \
        "selp.b32 %0, 1, 0, p;\n\t}"                                              \
        : "=r"(_d) : "r"(_m), "r"(_p) : "memory");                                \
    if (!_d) {                                                                    \
        asm volatile("{\n\t.reg .pred P1;\n\t"                                    \
            "WAIT_LOOP_%=:\n\t"                                                   \
            "mbarrier.try_wait.parity.acquire.cta.shared::cta.b64 P1, [%0], %1, 0x989680;\n\t" \
            "@P1 bra.uni WAIT_DONE_%=;\n\t"                                       \
            "bra.uni WAIT_LOOP_%=;\n\t"                                           \
            "WAIT_DONE_%=:\n\t}"                                                  \
            :: "r"(_m), "r"(_p) : "memory");                                      \
    }                                                                             \
} while (0)

// relaxed wait: OK for producer whose post-wait smem writes are async-proxy (bulk DMA)
#define MBARRIER_WAIT_PARITY_RELAXED(addr, parity) do {                           \
    uint32_t _m = (uint32_t)(addr); uint32_t _p = (uint32_t)(parity); uint32_t _d;\
    asm volatile("{\n\t.reg .pred p;\n\t"                                         \
        "mbarrier.try_wait.parity.relaxed.cta.shared::cta.b64 p, [%1], %2;\n\t"   \
        "selp.b32 %0, 1, 0, p;\n\t}"                                              \
        : "=r"(_d) : "r"(_m), "r"(_p) : "memory");                                \
    if (!_d) {                                                                    \
        asm volatile("{\n\t.reg .pred P1;\n\t"                                    \
            "WAIT_LOOP_%=:\n\t"                                                   \
            "mbarrier.try_wait.parity.relaxed.cta.shared::cta.b64 P1, [%0], %1, 0x989680;\n\t" \
            "@P1 bra.uni WAIT_DONE_%=;\n\t"                                       \
            "bra.uni WAIT_LOOP_%=;\n\t"                                           \
            "WAIT_DONE_%=:\n\t}"                                                  \
            :: "r"(_m), "r"(_p) : "memory");                                      \
    }                                                                             \
} while (0)

__device__ __forceinline__ void bulk_g2s(uint32_t dst, const void* src,
                                         uint32_t bytes, uint32_t mbar) {
    asm volatile(
        "cp.async.bulk.shared::cluster.global.mbarrier::complete_tx::bytes [%0], [%1], %2, [%3];"
        :: "r"(dst), "l"(src), "r"(bytes), "r"(mbar) : "memory");
}

// fp16 HMMA: D(f32, m16n8) += A(f16, m16k16) * B(f16, k16n8)
__device__ __forceinline__ void mma_f16(float* d, const uint32_t* a, const uint32_t* b) {
    asm volatile(
        "mma.sync.aligned.m16n8k16.row.col.f32.f16.f16.f32 "
        "{%0,%1,%2,%3}, {%4,%5,%6,%7}, {%8,%9}, {%0,%1,%2,%3};"
        : "+f"(d[0]), "+f"(d[1]), "+f"(d[2]), "+f"(d[3])
        : "r"(a[0]), "r"(a[1]), "r"(a[2]), "r"(a[3]), "r"(b[0]), "r"(b[1]));
}

__device__ __forceinline__ uint32_t h2(float a, float b) {
    __half2 h = __floats2half2_rn(a, b);
    return *reinterpret_cast<uint32_t*>(&h);
}

// ---------------------------------------------------------------------------
// Fused pack kernel (identical to R6/R9; paired-B layout).
// ---------------------------------------------------------------------------
__global__ void __launch_bounds__(256) pack_kernel(const float* __restrict__ x,
                                                   const int* __restrict__ wq) {
    if (blockIdx.x < 32768) {
        const int t = blockIdx.x * 256 + threadIdx.x;
        const int chunk = t >> 10, slot = t & 1023;
        const int mtile = chunk >> 6, ks = chunk & 63;
        const int lane = slot & 31, mt = (slot >> 5) & 1, kk = (slot >> 6) & 3, mw = slot >> 8;
        const int m0 = mtile * 128 + mw * 32 + mt * 16 + (lane >> 2);
        const int kb = ks * 64 + kk * 16 + (lane & 3) * 2;
        const float* p0 = x + (size_t)m0 * K_TOTAL + kb;
        const float* p8 = p0 + 8 * K_TOTAL;
        const float2 f00 = *reinterpret_cast<const float2*>(p0);
        const float2 f10 = *reinterpret_cast<const float2*>(p8);
        const float2 f01 = *reinterpret_cast<const float2*>(p0 + 8);
        const float2 f11 = *reinterpret_cast<const float2*>(p8 + 8);
        uint4 v;
        v.x = h2(f00.x, f00.y);
        v.y = h2(f10.x, f10.y);
        v.z = h2(f01.x, f01.y);
        v.w = h2(f11.x, f11.y);
        *reinterpret_cast<uint4*>(g_A + ((size_t)chunk << 14) + ((size_t)slot << 4)) = v;
    } else {
        const int t = (blockIdx.x - 32768) * 256 + threadIdx.x;
        const int chunk = t >> 10, slot = t & 1023;
        const int ntile = chunk >> 6, ks = chunk & 63;
        const int lane = slot & 31, p = (slot >> 5) & 3, kk = (slot >> 7) & 3, nw = slot >> 9;
        const int n0 = ntile * 128 + nw * 64 + p * 16 + (lane >> 2);
        const int kb = ks * 64 + kk * 16 + (lane & 3) * 2;
        const int* qa = wq + (size_t)n0 * K_TOTAL + kb;
        const int* qb = qa + 8 * (size_t)K_TOTAL;
        const int2 a0 = *reinterpret_cast<const int2*>(qa);
        const int2 a1 = *reinterpret_cast<const int2*>(qa + 8);
        const int2 b0 = *reinterpret_cast<const int2*>(qb);
        const int2 b1 = *reinterpret_cast<const int2*>(qb + 8);
        uint4 v;
        v.x = h2((float)a0.x, (float)a0.y);
        v.y = h2((float)a1.x, (float)a1.y);
        v.z = h2((float)b0.x, (float)b0.y);
        v.w = h2((float)b1.x, (float)b1.y);
        *reinterpret_cast<uint4*>(g_B + ((size_t)chunk << 14) + ((size_t)slot << 4)) = v;
    }
}

// ---------------------------------------------------------------------------
// GEMM: CTA 128x128, 256 thr = 8 warps (4m x 2n), warp tile 32x64.
// Decoupled ring: full[s] (count 1, tx) / empty[s] (count 8).
// kk=3: consume-all-registers MMA prefix (9 MMAs) -> SAFE early release ->
// hoisted full-wait -> remaining 7 MMAs. Direct-STG epilogue.
// ---------------------------------------------------------------------------
__global__ void __launch_bounds__(256, 2) qgemm_kernel(
    const float* __restrict__ scale_p,
    const float* __restrict__ bias,
    float* __restrict__ out)
{
    extern __shared__ __align__(128) unsigned char smem[];
    const uint32_t sb = smem_u32(smem);
    const int tid = threadIdx.x, lane = tid & 31, warp = tid >> 5;
    const int mw = warp & 3, nw = warp >> 2;
    const int ntile = blockIdx.x, mtile = blockIdx.y;

    // mbarriers: full[s] @ sb + s*16, empty[s] @ sb + s*16 + 8
    if (tid < STAGES) {
        MBARRIER_INIT(sb + tid * 16, 1);        // full: tx-completion
        MBARRIER_INIT(sb + tid * 16 + 8, 8);    // empty: 8 warp arrivals
    }
    float* sbias = reinterpret_cast<float*>(smem + SMEM_BIAS);
    if (tid < 128) sbias[tid] = bias[ntile * 128 + tid];
    const float qs = scale_p[0];
    __syncthreads();

    const unsigned char* gA = g_A + (((size_t)mtile * NUM_KS) << 14);
    const unsigned char* gB = g_B + (((size_t)ntile * NUM_KS) << 14);

    // prologue: fill chunks 0..STAGES-2
    if (tid == 0) {
#pragma unroll
        for (int s = 0; s < STAGES - 1; s++) {
            const uint32_t mbar = sb + s * 16;
            const uint32_t dst  = sb + SMEM_STAGE0 + s * STAGE_BYTES;
            MBARRIER_EXPECT_TX(mbar, STAGE_BYTES);
            bulk_g2s(dst, gA + ((size_t)s << 14), A_CHUNK_BYTES, mbar);
            bulk_g2s(dst + A_CHUNK_BYTES, gB + ((size_t)s << 14), B_CHUNK_BYTES, mbar);
        }
    }

    float acc[2][8][4];
#pragma unroll
    for (int mt = 0; mt < 2; mt++)
#pragma unroll
        for (int nt = 0; nt < 8; nt++)
#pragma unroll
            for (int j = 0; j < 4; j++) acc[mt][nt][j] = 0.0f;

    // wait for chunk 0 (later chunks' waits are hoisted into loop tails)
    MBARRIER_WAIT_PARITY(sb + 0 * 16, 0);

    for (int ks = 0; ks < NUM_KS; ks++) {
        const int s = ks % STAGES;

        // producer duty (tid 0): refill chunk ks+STAGES-1 into its stage
        if (tid == 0) {
            const int ks2 = ks + STAGES - 1;
            if (ks2 < NUM_KS) {
                const int s2 = ks2 % STAGES;
                if (ks2 >= STAGES) {
                    MBARRIER_WAIT_PARITY_RELAXED(sb + s2 * 16 + 8,
                                                 ((ks2 / STAGES) - 1) & 1);
                }
                const uint32_t mbar = sb + s2 * 16;
                const uint32_t dst  = sb + SMEM_STAGE0 + s2 * STAGE_BYTES;
                MBARRIER_EXPECT_TX(mbar, STAGE_BYTES);
                bulk_g2s(dst, gA + ((size_t)ks2 << 14), A_CHUNK_BYTES, mbar);
                bulk_g2s(dst + A_CHUNK_BYTES, gB + ((size_t)ks2 << 14),
                         B_CHUNK_BYTES, mbar);
            }
        }

        const unsigned char* st = smem + SMEM_STAGE0 + s * STAGE_BYTES;

#pragma unroll
        for (int kk = 0; kk < 4; kk++) {
            uint32_t afr[2][4];
            uint32_t bfr[8][2];
#pragma unroll
            for (int mt = 0; mt < 2; mt++) {
                const uint4 v = *reinterpret_cast<const uint4*>(
                    st + ((((mw * 4 + kk) * 2 + mt) * 32 + lane) << 4));
                afr[mt][0] = v.x; afr[mt][1] = v.y; afr[mt][2] = v.z; afr[mt][3] = v.w;
            }
#pragma unroll
            for (int p = 0; p < 4; p++) {
                const uint4 v = *reinterpret_cast<const uint4*>(
                    st + A_CHUNK_BYTES + ((((nw * 4 + kk) * 4 + p) * 32 + lane) << 4));
                bfr[2 * p][0]     = v.x; bfr[2 * p][1]     = v.y;
                bfr[2 * p + 1][0] = v.z; bfr[2 * p + 1][1] = v.w;
            }

            if (kk < 3) {
#pragma unroll
                for (int mt = 0; mt < 2; mt++)
#pragma unroll
                    for (int nt = 0; nt < 8; nt++)
                        mma_f16(acc[mt][nt], afr[mt], bfr[nt]);
            } else {
                // ---- consume-all prefix: these 9 MMAs touch every fragment
                // register (afr[0], afr[1], bfr[0..7]); issuing the 9th proves
                // ALL of this chunk's LDS have completed their SMEM reads.
#pragma unroll
                for (int nt = 0; nt < 8; nt++)
                    mma_f16(acc[0][nt], afr[0], bfr[nt]);
                mma_f16(acc[1][0], afr[1], bfr[0]);

                // SAFE early release of stage s
                if (lane == 0) MBARRIER_ARRIVE(sb + s * 16 + 8);
                // hoisted full-wait for next chunk (wakeup overlapped by the
                // remaining MMA drain)
                if (ks + 1 < NUM_KS) {
                    const int ns = (ks + 1) % STAGES;
                    MBARRIER_WAIT_PARITY(sb + ns * 16, ((ks + 1) / STAGES) & 1);
                }

#pragma unroll
                for (int nt = 1; nt < 8; nt++)
                    mma_f16(acc[1][nt], afr[1], bfr[nt]);
            }
        }
    }

    // ------------------------------ epilogue ------------------------------
    // Direct fragment-order stores: lanes 0..3 of a row cover 8 contiguous
    // floats = one full 32B sector; a warp instruction covers 8 rows x 32B
    // fully-utilized sectors.
    const int orow = mtile * 128 + mw * 32 + (lane >> 2);
    const int ocol = ntile * 128 + nw * 64 + (lane & 3) * 2;
    float* const obase = out + (size_t)orow * N_TOTAL + ocol;

#pragma unroll
    for (int mt = 0; mt < 2; mt++)
#pragma unroll
        for (int nt = 0; nt < 8; nt++) {
            const int col = nw * 64 + (lane & 3) * 2 + nt * 8;
            float2 lo = make_float2(acc[mt][nt][0] * qs + sbias[col],
                                    acc[mt][nt][1] * qs + sbias[col + 1]);
            float2 hi = make_float2(acc[mt][nt][2] * qs + sbias[col],
                                    acc[mt][nt][3] * qs + sbias[col + 1]);
            float* p = obase + (size_t)(mt * 16) * N_TOTAL + nt * 8;
            *reinterpret_cast<float2*>(p)                    = lo;
            *reinterpret_cast<float2*>(p + 8ull * N_TOTAL)   = hi;
        }
}

// ---------------------------------------------------------------------------
extern "C" void kernel_launch(void* const* d_in, const int* in_sizes, int n_in,
                              void* d_out, int out_size) {
    const float* x     = (const float*)d_in[0];
    const int*   wq    = (const int*)d_in[1];
    const float* scale = (const float*)d_in[2];
    const float* bias  = (const float*)d_in[3];
    float* out = (float*)d_out;

    pack_kernel<<<40960, 256>>>(x, wq);   // 32768 A-blocks + 8192 B-blocks

    cudaFuncSetAttribute(qgemm_kernel,
                         cudaFuncAttributeMaxDynamicSharedMemorySize, DYN_SMEM);
    dim3 grid(NUM_NT, NUM_MT);   // ntile fast: wave shares A rows, B L2-resident
    qgemm_kernel<<<grid, 256, DYN_SMEM>>>(scale, bias, out);
}

// round 12
// speedup vs baseline: 1.0088x; 1.0088x over previous
#include <cuda_runtime.h>
#include <cuda_fp16.h>
#include <cstdint>

// ============================================================================
// QuantizedLinear, sm_103 base-PTX build (no tcgen05 in this toolchain).
// R3: classic fp16 HMMA native, 1437us (66.5%).  R4: 2 CTAs/SM -> 1269us.
// R5: decoupled mbarrier ring -> 1126us (86.1%). R6: hoisted wait -> 1117us
//     (86.6%, rel_err bit-stable 2.0903e-4 across R4-R6).
// R7: rotation (DVFS noise).  R8: persistent 2-tile: regression, reverted.
// R9/R10: EARLY stage release (both variants) -> ~1112us but rel_err jumped
//     to unstable ~6e-4 — even the dependency-proven consume-before-release
//     variant. Conclusion: early empty-arrive is empirically unsafe on this
//     part; reverted. (Direct-STG epilogue is value-identical and innocent.)
// R11 = R6 sync structure EXACTLY (release at end of chunk, after all MMAs)
//       + direct-STG epilogue (deletes SMEM transpose + 2 syncthreads).
//   x -> fp16 (rel sigma ~1.7e-4), wq (0..126) -> fp16 exact,
//   y = (x_h @ w_h^T)*scale + bias, fp32 accum.
// ============================================================================

#define M_TOTAL 16384
#define N_TOTAL 4096
#define K_TOTAL 4096
#define NUM_KS  64            // K chunks of 64
#define NUM_MT  128           // M tiles of 128
#define NUM_NT  32            // N tiles of 128
#define STAGES  3

#define A_CHUNK_BYTES 16384   // 128m x 64k fp16, frag-ordered
#define B_CHUNK_BYTES 16384   // 128n x 64k fp16, frag-ordered (paired 16B slots)
#define STAGE_BYTES   (A_CHUNK_BYTES + B_CHUNK_BYTES)   // 32768

#define SMEM_BIAS   512
#define SMEM_STAGE0 1024
#define DYN_SMEM    (SMEM_STAGE0 + STAGES * STAGE_BYTES)  // 99328 -> 2 CTAs/SM

__device__ __align__(1024) unsigned char g_A[(size_t)NUM_MT * NUM_KS * A_CHUNK_BYTES]; // 128 MB
__device__ __align__(1024) unsigned char g_B[(size_t)NUM_NT * NUM_KS * B_CHUNK_BYTES]; //  32 MB

// ---------------------------------------------------------------------------
__device__ __forceinline__ uint32_t smem_u32(const void* p) {
    uint32_t a;
    asm("{ .reg .u64 t; cvta.to.shared.u64 t, %1; cvt.u32.u64 %0, t; }" : "=r"(a) : "l"(p));
    return a;
}

#define MBARRIER_INIT(addr, cnt) \
    asm volatile("mbarrier.init.shared.b64 [%0], %1;" :: "r"((uint32_t)(addr)), "r"((uint32_t)(cnt)) : "memory")
#define MBARRIER_EXPECT_TX(addr, bytes) \
    asm volatile("mbarrier.arrive.expect_tx.shared.b64 _, [%0], %1;" :: "r"((uint32_t)(addr)), "r"((uint32_t)(bytes)) : "memory")
#define MBARRIER_ARRIVE(addr) \
    asm volatile("mbarrier.arrive.shared.b64 _, [%0];" :: "r"((uint32_t)(addr)) : "memory")

#define MBARRIER_WAIT_PARITY(addr, parity) do {                                   \
    uint32_t _m = (uint32_t)(addr); uint32_t _p = (uint32_t)(parity); uint32_t _d;\
    asm volatile("{\n\t.reg .pred p;\n\t"                                         \
        "mbarrier.try_wait.parity.acquire.cta.shared::cta.b64 p, [%1], %2;\n\t"   \
        "selp.b32 %0, 1, 0, p;\n\t}"                                              \
        : "=r"(_d) : "r"(_m), "r"(_p) : "memory");                                \
    if (!_d) {                                                                    \
        asm volatile("{\n\t.reg .pred P1;\n\t"                                    \
            "WAIT_LOOP_%=:\n\t"                                                   \
            "mbarrier.try_wait.parity.acquire.cta.shared::cta.b64 P1, [%0], %1, 0x989680;\n\t" \
            "@P1 bra.uni WAIT_DONE_%=;\n\t"                                       \
            "bra.uni WAIT_LOOP_%=;\n\t"                                           \
            "WAIT_DONE_%=:\n\t}"                                                  \
            :: "r"(_m), "r"(_p) : "memory");                                      \
    }                                                                             \
} while (0)

// relaxed wait: OK for producer whose post-wait smem writes are async-proxy (bulk DMA)
#define MBARRIER_WAIT_PARITY_RELAXED(addr, parity) do {                           \
    uint32_t _m = (uint32_t)(addr); uint32_t _p = (uint32_t)(parity); uint32_t _d;\
    asm volatile("{\n\t.reg .pred p;\n\t"                                         \
        "mbarrier.try_wait.parity.relaxed.cta.shared::cta.b64 p, [%1], %2;\n\t"   \
        "selp.b32 %0, 1, 0, p;\n\t}"                                              \
        : "=r"(_d) : "r"(_m), "r"(_p) : "memory");                                \
    if (!_d) {                                                                    \
        asm volatile("{\n\t.reg .pred P1;\n\t"                                    \
            "WAIT_LOOP_%=:\n\t"                                                   \
            "mbarrier.try_wait.parity.relaxed.cta.shared::cta.b64 P1, [%0], %1, 0x989680;\n\t" \
            "@P1 bra.uni WAIT_DONE_%=;\n\t"                                       \
            "bra.uni WAIT_LOOP_%=;\n\t"                                           \
            "WAIT_DONE_%=:\n\t}"                                                  \
            :: "r"(_m), "r"(_p) : "memory");                                      \
    }                                                                             \
} while (0)

__device__ __forceinline__ void bulk_g2s(uint32_t dst, const void* src,
                                         uint32_t bytes, uint32_t mbar) {
    asm volatile(
        "cp.async.bulk.shared::cluster.global.mbarrier::complete_tx::bytes [%0], [%1], %2, [%3];"
        :: "r"(dst), "l"(src), "r"(bytes), "r"(mbar) : "memory");
}

// fp16 HMMA: D(f32, m16n8) += A(f16, m16k16) * B(f16, k16n8)
__device__ __forceinline__ void mma_f16(float* d, const uint32_t* a, const uint32_t* b) {
    asm volatile(
        "mma.sync.aligned.m16n8k16.row.col.f32.f16.f16.f32 "
        "{%0,%1,%2,%3}, {%4,%5,%6,%7}, {%8,%9}, {%0,%1,%2,%3};"
        : "+f"(d[0]), "+f"(d[1]), "+f"(d[2]), "+f"(d[3])
        : "r"(a[0]), "r"(a[1]), "r"(a[2]), "r"(a[3]), "r"(b[0]), "r"(b[1]));
}

__device__ __forceinline__ uint32_t h2(float a, float b) {
    __half2 h = __floats2half2_rn(a, b);
    return *reinterpret_cast<uint32_t*>(&h);
}

// ---------------------------------------------------------------------------
// Fused pack kernel (identical to R6; paired-B layout).
// ---------------------------------------------------------------------------
__global__ void __launch_bounds__(256) pack_kernel(const float* __restrict__ x,
                                                   const int* __restrict__ wq) {
    if (blockIdx.x < 32768) {
        const int t = blockIdx.x * 256 + threadIdx.x;
        const int chunk = t >> 10, slot = t & 1023;
        const int mtile = chunk >> 6, ks = chunk & 63;
        const int lane = slot & 31, mt = (slot >> 5) & 1, kk = (slot >> 6) & 3, mw = slot >> 8;
        const int m0 = mtile * 128 + mw * 32 + mt * 16 + (lane >> 2);
        const int kb = ks * 64 + kk * 16 + (lane & 3) * 2;
        const float* p0 = x + (size_t)m0 * K_TOTAL + kb;
        const float* p8 = p0 + 8 * K_TOTAL;
        const float2 f00 = *reinterpret_cast<const float2*>(p0);
        const float2 f10 = *reinterpret_cast<const float2*>(p8);
        const float2 f01 = *reinterpret_cast<const float2*>(p0 + 8);
        const float2 f11 = *reinterpret_cast<const float2*>(p8 + 8);
        uint4 v;
        v.x = h2(f00.x, f00.y);
        v.y = h2(f10.x, f10.y);
        v.z = h2(f01.x, f01.y);
        v.w = h2(f11.x, f11.y);
        *reinterpret_cast<uint4*>(g_A + ((size_t)chunk << 14) + ((size_t)slot << 4)) = v;
    } else {
        const int t = (blockIdx.x - 32768) * 256 + threadIdx.x;
        const int chunk = t >> 10, slot = t & 1023;
        const int ntile = chunk >> 6, ks = chunk & 63;
        const int lane = slot & 31, p = (slot >> 5) & 3, kk = (slot >> 7) & 3, nw = slot >> 9;
        const int n0 = ntile * 128 + nw * 64 + p * 16 + (lane >> 2);
        const int kb = ks * 64 + kk * 16 + (lane & 3) * 2;
        const int* qa = wq + (size_t)n0 * K_TOTAL + kb;
        const int* qb = qa + 8 * (size_t)K_TOTAL;
        const int2 a0 = *reinterpret_cast<const int2*>(qa);
        const int2 a1 = *reinterpret_cast<const int2*>(qa + 8);
        const int2 b0 = *reinterpret_cast<const int2*>(qb);
        const int2 b1 = *reinterpret_cast<const int2*>(qb + 8);
        uint4 v;
        v.x = h2((float)a0.x, (float)a0.y);
        v.y = h2((float)a1.x, (float)a1.y);
        v.z = h2((float)b0.x, (float)b0.y);
        v.w = h2((float)b1.x, (float)b1.y);
        *reinterpret_cast<uint4*>(g_B + ((size_t)chunk << 14) + ((size_t)slot << 4)) = v;
    }
}

// ---------------------------------------------------------------------------
// GEMM: CTA 128x128, 256 thr = 8 warps (4m x 2n), warp tile 32x64.
// Decoupled ring: full[s] (count 1, tx) / empty[s] (count 8).
// R6 sync structure: hoisted full-wait inside kk==3 (between loads and MMAs);
// stage release at END of chunk after all 16 MMAs (proven-safe ordering).
// Direct-STG epilogue (value-identical to the staged one).
// ---------------------------------------------------------------------------
__global__ void __launch_bounds__(256, 2) qgemm_kernel(
    const float* __restrict__ scale_p,
    const float* __restrict__ bias,
    float* __restrict__ out)
{
    extern __shared__ __align__(128) unsigned char smem[];
    const uint32_t sb = smem_u32(smem);
    const int tid = threadIdx.x, lane = tid & 31, warp = tid >> 5;
    const int mw = warp & 3, nw = warp >> 2;
    const int ntile = blockIdx.x, mtile = blockIdx.y;

    // mbarriers: full[s] @ sb + s*16, empty[s] @ sb + s*16 + 8
    if (tid < STAGES) {
        MBARRIER_INIT(sb + tid * 16, 1);        // full: tx-completion
        MBARRIER_INIT(sb + tid * 16 + 8, 8);    // empty: 8 warp arrivals
    }
    float* sbias = reinterpret_cast<float*>(smem + SMEM_BIAS);
    if (tid < 128) sbias[tid] = bias[ntile * 128 + tid];
    const float qs = scale_p[0];
    __syncthreads();

    const unsigned char* gA = g_A + (((size_t)mtile * NUM_KS) << 14);
    const unsigned char* gB = g_B + (((size_t)ntile * NUM_KS) << 14);

    // prologue: fill chunks 0..STAGES-2
    if (tid == 0) {
#pragma unroll
        for (int s = 0; s < STAGES - 1; s++) {
            const uint32_t mbar = sb + s * 16;
            const uint32_t dst  = sb + SMEM_STAGE0 + s * STAGE_BYTES;
            MBARRIER_EXPECT_TX(mbar, STAGE_BYTES);
            bulk_g2s(dst, gA + ((size_t)s << 14), A_CHUNK_BYTES, mbar);
            bulk_g2s(dst + A_CHUNK_BYTES, gB + ((size_t)s << 14), B_CHUNK_BYTES, mbar);
        }
    }

    float acc[2][8][4];
#pragma unroll
    for (int mt = 0; mt < 2; mt++)
#pragma unroll
        for (int nt = 0; nt < 8; nt++)
#pragma unroll
            for (int j = 0; j < 4; j++) acc[mt][nt][j] = 0.0f;

    // wait for chunk 0 (later chunks' waits are hoisted into loop tails)
    MBARRIER_WAIT_PARITY(sb + 0 * 16, 0);

    for (int ks = 0; ks < NUM_KS; ks++) {
        const int s = ks % STAGES;

        // producer duty (tid 0): refill chunk ks+STAGES-1 into its stage
        if (tid == 0) {
            const int ks2 = ks + STAGES - 1;
            if (ks2 < NUM_KS) {
                const int s2 = ks2 % STAGES;
                if (ks2 >= STAGES) {
                    MBARRIER_WAIT_PARITY_RELAXED(sb + s2 * 16 + 8,
                                                 ((ks2 / STAGES) - 1) & 1);
                }
                const uint32_t mbar = sb + s2 * 16;
                const uint32_t dst  = sb + SMEM_STAGE0 + s2 * STAGE_BYTES;
                MBARRIER_EXPECT_TX(mbar, STAGE_BYTES);
                bulk_g2s(dst, gA + ((size_t)ks2 << 14), A_CHUNK_BYTES, mbar);
                bulk_g2s(dst + A_CHUNK_BYTES, gB + ((size_t)ks2 << 14),
                         B_CHUNK_BYTES, mbar);
            }
        }

        const unsigned char* st = smem + SMEM_STAGE0 + s * STAGE_BYTES;

#pragma unroll
        for (int kk = 0; kk < 4; kk++) {
            uint32_t afr[2][4];
            uint32_t bfr[8][2];
#pragma unroll
            for (int mt = 0; mt < 2; mt++) {
                const uint4 v = *reinterpret_cast<const uint4*>(
                    st + ((((mw * 4 + kk) * 2 + mt) * 32 + lane) << 4));
                afr[mt][0] = v.x; afr[mt][1] = v.y; afr[mt][2] = v.z; afr[mt][3] = v.w;
            }
#pragma unroll
            for (int p = 0; p < 4; p++) {
                const uint4 v = *reinterpret_cast<const uint4*>(
                    st + A_CHUNK_BYTES + ((((nw * 4 + kk) * 4 + p) * 32 + lane) << 4));
                bfr[2 * p][0]     = v.x; bfr[2 * p][1]     = v.y;
                bfr[2 * p + 1][0] = v.z; bfr[2 * p + 1][1] = v.w;
            }

            // hoisted full-wait for NEXT chunk (wakeup overlapped by MMA drain).
            // NOTE: stage release stays at END of chunk — early release
            // empirically corrupts (R9/R10).
            if (kk == 3 && ks + 1 < NUM_KS) {
                const int ns = (ks + 1) % STAGES;
                MBARRIER_WAIT_PARITY(sb + ns * 16, ((ks + 1) / STAGES) & 1);
            }

#pragma unroll
            for (int mt = 0; mt < 2; mt++)
#pragma unroll
                for (int nt = 0; nt < 8; nt++)
                    mma_f16(acc[mt][nt], afr[mt], bfr[nt]);
        }

        // this warp is done with stage s (after ALL MMAs — proven-safe point)
        if (lane == 0) MBARRIER_ARRIVE(sb + s * 16 + 8);
    }

    // ------------------------------ epilogue ------------------------------
    // Direct fragment-order stores: lanes 0..3 of a row cover 8 contiguous
    // floats = one full 32B sector; a warp instruction covers 8 rows x 32B
    // fully-utilized sectors. Value-identical to the staged epilogue.
    const int orow = mtile * 128 + mw * 32 + (lane >> 2);
    const int ocol = ntile * 128 + nw * 64 + (lane & 3) * 2;
    float* const obase = out + (size_t)orow * N_TOTAL + ocol;

#pragma unroll
    for (int mt = 0; mt < 2; mt++)
#pragma unroll
        for (int nt = 0; nt < 8; nt++) {
            const int col = nw * 64 + (lane & 3) * 2 + nt * 8;
            float2 lo = make_float2(acc[mt][nt][0] * qs + sbias[col],
                                    acc[mt][nt][1] * qs + sbias[col + 1]);
            float2 hi = make_float2(acc[mt][nt][2] * qs + sbias[col],
                                    acc[mt][nt][3] * qs + sbias[col + 1]);
            float* p = obase + (size_t)(mt * 16) * N_TOTAL + nt * 8;
            *reinterpret_cast<float2*>(p)                    = lo;
            *reinterpret_cast<float2*>(p + 8ull * N_TOTAL)   = hi;
        }
}

// ---------------------------------------------------------------------------
extern "C" void kernel_launch(void* const* d_in, const int* in_sizes, int n_in,
                              void* d_out, int out_size) {
    const float* x     = (const float*)d_in[0];
    const int*   wq    = (const int*)d_in[1];
    const float* scale = (const float*)d_in[2];
    const float* bias  = (const float*)d_in[3];
    float* out = (float*)d_out;

    pack_kernel<<<40960, 256>>>(x, wq);   // 32768 A-blocks + 8192 B-blocks

    cudaFuncSetAttribute(qgemm_kernel,
                         cudaFuncAttributeMaxDynamicSharedMemorySize, DYN_SMEM);
    dim3 grid(NUM_NT, NUM_MT);   // ntile fast: wave shares A rows, B L2-resident
    qgemm_kernel<<<grid, 256, DYN_SMEM>>>(scale, bias, out);
}